// round 15
// baseline (speedup 1.0000x reference)
#include <cuda_runtime.h>
#include <cuda_fp16.h>
#include <cstdint>
#include <math.h>

// Problem constants
#define BB   128
#define TT   20
#define DIN  200
#define HH   1024
#define LL   12
#define NOUT 1095
#define MM   (BB * TT)      // 2560
#define N3H  (3 * HH)       // 3072
#define NPAD4 1152          // W4 N padded to multiple of 128

// ---------------------------------------------------------------------------
// Scratch (device globals)
// ---------------------------------------------------------------------------
__device__ float g_Ux[MM * HH];           // x_tilde (fp32)
__device__ __half g_Ufr[MM * 2 * HH];     // gate pre-activations (fp16 raw)
__device__ __half g_Ahi[MM * HH];     // activations [T,B] order, fp16 hi
__device__ __half g_Alo[MM * HH];     // fp16 lo (residual)
__device__ __half g_Bhi[MM * HH];     // last-layer output, [B,T] order
__device__ __half g_Blo[MM * HH];
__device__ __half g_Wt[LL * N3H * HH];   // weights fp16 (truncated), K-major
__device__ __half g_W3t[HH * HH];
__device__ __half g_W4t[NPAD4 * HH];

// ---------------------------------------------------------------------------
// Helpers (base-ISA: cp.async, ldmatrix, mma.sync)
// ---------------------------------------------------------------------------
__device__ __forceinline__ uint32_t smem_u32(const void* p) {
    uint32_t a;
    asm("{ .reg .u64 t; cvta.to.shared.u64 t, %1; cvt.u32.u64 %0, t; }"
        : "=r"(a) : "l"(p));
    return a;
}

#define SWZ128(o) ((o) ^ (((o) >> 3) & 0x70))
#define SWZ64(o)  ((o) ^ (((o) >> 3) & 0x30))

__device__ __forceinline__ void cp_async16(uint32_t dst, const void* src) {
    asm volatile("cp.async.cg.shared.global [%0], [%1], 16;" :: "r"(dst), "l"(src));
}
__device__ __forceinline__ void cp_commit() {
    asm volatile("cp.async.commit_group;" ::: "memory");
}
__device__ __forceinline__ void cp_wait1() {
    asm volatile("cp.async.wait_group 1;" ::: "memory");
}
__device__ __forceinline__ void cp_wait2() {
    asm volatile("cp.async.wait_group 2;" ::: "memory");
}

__device__ __forceinline__ void ldsm_x4(uint32_t* r, uint32_t addr) {
    asm volatile("ldmatrix.sync.aligned.m8n8.x4.shared.b16 {%0,%1,%2,%3}, [%4];"
                 : "=r"(r[0]), "=r"(r[1]), "=r"(r[2]), "=r"(r[3]) : "r"(addr));
}

__device__ __forceinline__ void mma_f16(float* d, const uint32_t* a, const uint32_t* b) {
    asm volatile(
        "mma.sync.aligned.m16n8k16.row.col.f32.f16.f16.f32 "
        "{%0,%1,%2,%3}, {%4,%5,%6,%7}, {%8,%9}, {%0,%1,%2,%3};"
        : "+f"(d[0]), "+f"(d[1]), "+f"(d[2]), "+f"(d[3])
        : "r"(a[0]), "r"(a[1]), "r"(a[2]), "r"(a[3]), "r"(b[0]), "r"(b[1]));
}

__device__ __forceinline__ void split_h(float v, __half& hi, __half& lo) {
    hi = __float2half_rn(v);
    lo = __float2half_rn(v - __half2float(hi));
}

#define GK HH

// ===========================================================================
// gemm_sru: SRU-layer GEMM, BM=128, BN=128, BK=32, NSTAGE=4 (24KB/stage,
// 96KB smem -> 2 CTAs/SM). Halves B re-reads vs BM=64 (L2 traffic 504->378MB).
// Cols < HH: 2-MMA hi/lo A split -> Ux fp32. Cols >= HH: 1-MMA -> Ufr fp16.
// 8 warps as 2(m) x 4(n); warp tile 64x32; b-fragments streamed (reg cap 128).
// ===========================================================================
#define SKSTEPS  (GK / 32)         // 32
#define S_TILE   8192              // 128 rows x 32 k x 2B (A half or B)
#define S_STAGE  (3 * S_TILE)      // 24576
#define S_NSTAGE 4
#define S_GSMEM  (S_NSTAGE * S_STAGE)   // 98304

__device__ __forceinline__ void s_load_stage(
    uint32_t sbase, int st, int k0, int tid, int bm, int bn, bool loadLo,
    const __half* __restrict__ Ahi, const __half* __restrict__ Alo,
    const __half* __restrict__ Bh)
{
    uint32_t base = sbase + (st & (S_NSTAGE - 1)) * S_STAGE;
#pragma unroll
    for (int p = 0; p < 2; p++) {              // A: 128 rows x 4 chunks = 512
        int idx = tid + p * 256;
        int row = idx >> 2, ch = idx & 3;
        uint32_t off = SWZ64((uint32_t)(row * 64 + ch * 16));
        size_t ga = (size_t)(bm + row) * GK + k0 + ch * 8;
        cp_async16(base + off, Ahi + ga);
        if (loadLo) cp_async16(base + S_TILE + off, Alo + ga);
    }
#pragma unroll
    for (int p = 0; p < 2; p++) {              // B: 128 rows x 4 chunks = 512
        int idx = tid + p * 256;
        int row = idx >> 2, ch = idx & 3;
        uint32_t off = SWZ64((uint32_t)(row * 64 + ch * 16));
        size_t gb = (size_t)(bn + row) * GK + k0 + ch * 8;
        cp_async16(base + 2 * S_TILE + off, Bh + gb);
    }
}

__global__ __launch_bounds__(256, 2)
void gemm_sru(const __half* __restrict__ Ahi, const __half* __restrict__ Alo,
              const __half* __restrict__ Bh,
              float* __restrict__ Ux, __half* __restrict__ Ufr)
{
    extern __shared__ char smem[];
    const uint32_t sbase = smem_u32(smem);
    const int tid = threadIdx.x;
    const int wid = tid >> 5, lane = tid & 31;
    const int warp_m = wid & 1, warp_n = wid >> 1;   // 2 x 4, warp tile 64x32
    const int bm = blockIdx.y * 128;
    const int bn = blockIdx.x * 128;
    const bool useLo = (bn < HH);

    float acc[4][4][4];
#pragma unroll
    for (int i = 0; i < 4; i++)
#pragma unroll
        for (int j = 0; j < 4; j++)
#pragma unroll
            for (int q = 0; q < 4; q++) acc[i][j][q] = 0.f;

    // prologue: 3 stages in flight
    s_load_stage(sbase, 0, 0, tid, bm, bn, useLo, Ahi, Alo, Bh); cp_commit();
    s_load_stage(sbase, 1, 32, tid, bm, bn, useLo, Ahi, Alo, Bh); cp_commit();
    s_load_stage(sbase, 2, 64, tid, bm, bn, useLo, Ahi, Alo, Bh); cp_commit();

    const int a_r = (lane & 7) + ((lane >> 3) & 1) * 8;
    const int a_c = (lane >> 4);
    const int b_r = (lane & 7) + ((lane >> 4) & 1) * 8;
    const int b_c = (lane >> 3) & 1;

    for (int s = 0; s < SKSTEPS; s++) {
        cp_wait2();          // stage s ready (s+1, s+2 may still be in flight)
        __syncthreads();     // all warps done reading stage s-1

        if (s + 3 < SKSTEPS) {
            s_load_stage(sbase, s + 3, (s + 3) * 32, tid, bm, bn, useLo,
                         Ahi, Alo, Bh);
        }
        cp_commit();         // uniform group count (empty in tail)

        uint32_t stg = sbase + (s & (S_NSTAGE - 1)) * S_STAGE;
#pragma unroll
        for (int h = 0; h < 2; h++) {       // two k16 chunks of BK=32
            uint32_t a_hi[4][4], a_lo[4][4];
#pragma unroll
            for (int mt = 0; mt < 4; mt++) {
                int row = warp_m * 64 + mt * 16 + a_r;
                uint32_t off = SWZ64((uint32_t)(row * 64 + (2 * h + a_c) * 16));
                ldsm_x4(a_hi[mt], stg + off);
                if (useLo) ldsm_x4(a_lo[mt], stg + S_TILE + off);
            }
#pragma unroll
            for (int p = 0; p < 2; p++) {   // stream b fragments
                uint32_t b_h[4];
                int row = warp_n * 32 + p * 16 + b_r;
                uint32_t off = SWZ64((uint32_t)(row * 64 + (2 * h + b_c) * 16));
                ldsm_x4(b_h, stg + 2 * S_TILE + off);
#pragma unroll
                for (int mt = 0; mt < 4; mt++)
#pragma unroll
                    for (int q = 0; q < 2; q++) {
                        float* d = acc[mt][2 * p + q];
                        mma_f16(d, a_hi[mt], &b_h[2 * q]);
                        if (useLo) mma_f16(d, a_lo[mt], &b_h[2 * q]);
                    }
            }
        }
    }

    // epilogue (SRU mode)
    const int er = lane >> 2;
    const int ec = (lane & 3) * 2;
#pragma unroll
    for (int mt = 0; mt < 4; mt++) {
#pragma unroll
        for (int nt = 0; nt < 4; nt++) {
            int row = bm + warp_m * 64 + mt * 16 + er;
            int col = bn + warp_n * 32 + nt * 8 + ec;
            float* d = acc[mt][nt];
            if (col < HH) {
                *(float2*)(Ux + (size_t)row * HH + col) = make_float2(d[0], d[1]);
                *(float2*)(Ux + (size_t)(row + 8) * HH + col) = make_float2(d[2], d[3]);
            } else {
                int cg = col - HH;
                *(__half2*)(Ufr + (size_t)row * (2 * HH) + cg) =
                    __halves2half2(__float2half_rn(d[0]), __float2half_rn(d[1]));
                *(__half2*)(Ufr + (size_t)(row + 8) * (2 * HH) + cg) =
                    __halves2half2(__float2half_rn(d[2]), __float2half_rn(d[3]));
            }
        }
    }
}

// ===========================================================================
// gemm_mma (r12 config, fx/logits only): BM=64, BN=128, BK=64, NSTAGE=3.
// Full 2-MMA. C (+bias), optional fused relu+split to Ohi/Olo.
// ===========================================================================
#define KSTEPS  (GK / 64)          // 16
#define TILE_AH 8192               // 64 rows x 64 k x 2B (one A half)
#define TILE_BB 16384              // 128 rows x 64 k x 2B
#define STAGE_B (2 * TILE_AH + TILE_BB)   // 32768
#define NSTAGE  3
#define GSMEM   (NSTAGE * STAGE_B)        // 98304 -> 2 CTAs/SM

__device__ __forceinline__ void g_load_stage(
    uint32_t sbase, int st, int k0, int tid, int bm, int bn,
    const __half* __restrict__ Ahi, const __half* __restrict__ Alo,
    const __half* __restrict__ Bh)
{
    uint32_t base = sbase + (st % NSTAGE) * STAGE_B;
#pragma unroll
    for (int p = 0; p < 2; p++) {              // A: 64 rows x 8 chunks = 512
        int idx = tid + p * 256;
        int row = idx >> 3, ch = idx & 7;
        uint32_t off = SWZ128((uint32_t)(row * 128 + ch * 16));
        size_t ga = (size_t)(bm + row) * GK + k0 + ch * 8;
        cp_async16(base + off, Ahi + ga);
        cp_async16(base + TILE_AH + off, Alo + ga);
    }
#pragma unroll
    for (int p = 0; p < 4; p++) {              // B: 128 rows x 8 chunks = 1024
        int idx = tid + p * 256;
        int row = idx >> 3, ch = idx & 7;
        uint32_t off = SWZ128((uint32_t)(row * 128 + ch * 16));
        size_t gb = (size_t)(bn + row) * GK + k0 + ch * 8;
        cp_async16(base + 2 * TILE_AH + off, Bh + gb);
    }
}

__global__ __launch_bounds__(256, 2)
void gemm_mma(const __half* __restrict__ Ahi, const __half* __restrict__ Alo,
              const __half* __restrict__ Bh,
              const float* __restrict__ bias, float* __restrict__ C, int Nact,
              __half* __restrict__ Ohi, __half* __restrict__ Olo)
{
    extern __shared__ char smem[];
    const uint32_t sbase = smem_u32(smem);
    const int tid = threadIdx.x;
    const int wid = tid >> 5, lane = tid & 31;
    const int warp_m = wid & 1, warp_n = wid >> 1;   // 2 x 4, warp tile 32x32
    const int bm = blockIdx.y * 64;
    const int bn = blockIdx.x * 128;

    float acc[2][4][4];
#pragma unroll
    for (int i = 0; i < 2; i++)
#pragma unroll
        for (int j = 0; j < 4; j++)
#pragma unroll
            for (int q = 0; q < 4; q++) acc[i][j][q] = 0.f;

    g_load_stage(sbase, 0, 0, tid, bm, bn, Ahi, Alo, Bh); cp_commit();
    g_load_stage(sbase, 1, 64, tid, bm, bn, Ahi, Alo, Bh); cp_commit();

    const int a_r = (lane & 7) + ((lane >> 3) & 1) * 8;
    const int a_c = (lane >> 4);
    const int b_r = (lane & 7) + ((lane >> 4) & 1) * 8;
    const int b_c = (lane >> 3) & 1;

    for (int s = 0; s < KSTEPS; s++) {
        cp_wait1();
        __syncthreads();

        if (s + 2 < KSTEPS) {
            g_load_stage(sbase, s + 2, (s + 2) * 64, tid, bm, bn, Ahi, Alo, Bh);
        }
        cp_commit();

        uint32_t stg = sbase + (s % NSTAGE) * STAGE_B;
#pragma unroll
        for (int h = 0; h < 4; h++) {       // four k16 chunks of BK=64
            uint32_t a_hi[2][4], a_lo[2][4], b_h[2][4];
#pragma unroll
            for (int mt = 0; mt < 2; mt++) {
                int row = warp_m * 32 + mt * 16 + a_r;
                uint32_t off = SWZ128((uint32_t)(row * 128 + h * 32 + a_c * 16));
                ldsm_x4(a_hi[mt], stg + off);
                ldsm_x4(a_lo[mt], stg + TILE_AH + off);
            }
#pragma unroll
            for (int p = 0; p < 2; p++) {
                int row = warp_n * 32 + p * 16 + b_r;
                uint32_t off = SWZ128((uint32_t)(row * 128 + h * 32 + b_c * 16));
                ldsm_x4(b_h[p], stg + 2 * TILE_AH + off);
            }
#pragma unroll
            for (int mt = 0; mt < 2; mt++)
#pragma unroll
                for (int p = 0; p < 2; p++)
#pragma unroll
                    for (int q = 0; q < 2; q++) {
                        float* d = acc[mt][2 * p + q];
                        mma_f16(d, a_hi[mt], &b_h[p][2 * q]);
                        mma_f16(d, a_lo[mt], &b_h[p][2 * q]);
                    }
        }
    }

    // epilogue
    const int er = lane >> 2;
    const int ec = (lane & 3) * 2;
    const bool even_stride = (Nact & 1) == 0;
#pragma unroll
    for (int mt = 0; mt < 2; mt++) {
#pragma unroll
        for (int nt = 0; nt < 4; nt++) {
            int row = bm + warp_m * 32 + mt * 16 + er;
            int col = bn + warp_n * 32 + nt * 8 + ec;
            float* d = acc[mt][nt];
            if (even_stride) {
                float b0 = bias ? bias[col] : 0.f;
                float b1 = bias ? bias[col + 1] : 0.f;
                float v00 = d[0] + b0, v01 = d[1] + b1;
                float v10 = d[2] + b0, v11 = d[3] + b1;
                *(float2*)(C + (size_t)row * Nact + col)       = make_float2(v00, v01);
                *(float2*)(C + (size_t)(row + 8) * Nact + col) = make_float2(v10, v11);
                if (Ohi) {  // fused relu + fp16 hi/lo split (fx path)
                    float r00 = fmaxf(v00, 0.f), r01 = fmaxf(v01, 0.f);
                    float r10 = fmaxf(v10, 0.f), r11 = fmaxf(v11, 0.f);
                    __half h00, l00, h01, l01, h10, l10, h11, l11;
                    split_h(r00, h00, l00); split_h(r01, h01, l01);
                    split_h(r10, h10, l10); split_h(r11, h11, l11);
                    size_t i0 = (size_t)row * Nact + col;
                    size_t i1 = (size_t)(row + 8) * Nact + col;
                    *(__half2*)(Ohi + i0) = __halves2half2(h00, h01);
                    *(__half2*)(Ohi + i1) = __halves2half2(h10, h11);
                    *(__half2*)(Olo + i0) = __halves2half2(l00, l01);
                    *(__half2*)(Olo + i1) = __halves2half2(l10, l11);
                }
            } else {
                if (col < Nact) {
                    float b0 = bias ? bias[col] : 0.f;
                    C[(size_t)row * Nact + col]       = d[0] + b0;
                    C[(size_t)(row + 8) * Nact + col] = d[2] + b0;
                }
                if (col + 1 < Nact) {
                    float b1 = bias ? bias[col + 1] : 0.f;
                    C[(size_t)row * Nact + col + 1]       = d[1] + b1;
                    C[(size_t)(row + 8) * Nact + col + 1] = d[3] + b1;
                }
            }
        }
    }
}

// ---------------------------------------------------------------------------
// All weight transposes in ONE launch. blockIdx.z: 0..11 SRU, 12 W3, 13 W4.
// ---------------------------------------------------------------------------
__global__ __launch_bounds__(256)
void transpose_all(const float* __restrict__ sru_W,
                   const float* __restrict__ W3,
                   const float* __restrict__ W4,
                   __half* __restrict__ Wt,
                   __half* __restrict__ W3t,
                   __half* __restrict__ W4t)
{
    int z = blockIdx.z;
    const float* W;
    __half* hi;
    int Nsrc, Npad;
    if (z < LL) {
        W = sru_W + (size_t)z * HH * N3H;
        hi = Wt + (size_t)z * N3H * HH;
        Nsrc = N3H; Npad = N3H;
    } else if (z == LL) {
        W = W3; hi = W3t; Nsrc = HH; Npad = HH;
    } else {
        W = W4; hi = W4t; Nsrc = NOUT; Npad = NPAD4;
    }

    int nb = blockIdx.x * 32, kb = blockIdx.y * 64;
    if (nb >= Npad) return;

    __shared__ float t[64][33];
    int tx = threadIdx.x & 31;
    int ty = threadIdx.x >> 5;
    int n = nb + tx;
#pragma unroll
    for (int i = 0; i < 8; i++) {
        int kk = ty * 8 + i;
        t[kk][tx] = (n < Nsrc) ? W[(size_t)(kb + kk) * Nsrc + n] : 0.f;
    }
    __syncthreads();
#pragma unroll
    for (int p = 0; p < 4; p++) {
        int idx = threadIdx.x + p * 256;
        int nl = idx >> 5, kp = idx & 31;
        float v0 = t[2 * kp][nl];
        float v1 = t[2 * kp + 1][nl];
        size_t o = ((size_t)(nb + nl) * HH + kb) / 2 + kp;
        ((__half2*)hi)[o] = __halves2half2(__float2half_rn(v0), __float2half_rn(v1));
    }
}

// ---------------------------------------------------------------------------
// fp32 SGEMM for dense1 (K=200), writes fp16 hi/lo split only.
// ---------------------------------------------------------------------------
__global__ __launch_bounds__(256)
void sgemm_d1(const float* __restrict__ A, const float* __restrict__ W,
              const float* __restrict__ bias,
              __half* __restrict__ Chi, __half* __restrict__ Clo,
              int M, int N, int K)
{
    const int BMd = 128, BNd = 128, BKd = 8, TM = 8, TN = 8;
    __shared__ float As[BKd][BMd];
    __shared__ float Bs[BKd][BNd];
    const int bm = blockIdx.y * BMd, bn = blockIdx.x * BNd, tid = threadIdx.x;
    const int tx = (tid % 16) * TN, ty = (tid / 16) * TM;
    const int a_row = tid >> 1, a_kof = (tid & 1) * 4;
    const int b_row = tid >> 5, b_col = (tid & 31) * 4;

    int gm = bm + a_row;
    int arow_g = (gm % BB) * TT + gm / BB;
    const float* Aptr = A + (long)arow_g * K + a_kof;

    float acc[TM][TN];
#pragma unroll
    for (int i = 0; i < TM; i++)
#pragma unroll
        for (int j = 0; j < TN; j++) acc[i][j] = 0.f;

    for (int k0 = 0; k0 < K; k0 += BKd) {
        float4 av = *(const float4*)(Aptr + k0);
        As[a_kof + 0][a_row] = av.x;
        As[a_kof + 1][a_row] = av.y;
        As[a_kof + 2][a_row] = av.z;
        As[a_kof + 3][a_row] = av.w;
        float4 bv = *(const float4*)(W + (long)(k0 + b_row) * N + bn + b_col);
        *(float4*)&Bs[b_row][b_col] = bv;
        __syncthreads();
#pragma unroll
        for (int kk = 0; kk < BKd; kk++) {
            float a_reg[TM], b_reg[TN];
#pragma unroll
            for (int i = 0; i < TM; i++) a_reg[i] = As[kk][ty + i];
#pragma unroll
            for (int j = 0; j < TN; j++) b_reg[j] = Bs[kk][tx + j];
#pragma unroll
            for (int i = 0; i < TM; i++)
#pragma unroll
                for (int j = 0; j < TN; j++)
                    acc[i][j] = fmaf(a_reg[i], b_reg[j], acc[i][j]);
        }
        __syncthreads();
    }
#pragma unroll
    for (int i = 0; i < TM; i++) {
        int row = bm + ty + i;
#pragma unroll
        for (int j = 0; j < TN; j++) {
            int col = bn + tx + j;
            float v = acc[i][j] + bias[col];
            size_t idx = (size_t)row * N + col;
            __half h, l;
            split_h(v, h, l);
            Chi[idx] = h;
            Clo[idx] = l;
        }
    }
}

// ---------------------------------------------------------------------------
// SRU scan: x_tilde fp32 from Ux, gate pre-acts fp16 from Ufr (dense arrays).
// Bias + sigmoid here. Software prefetch, __expf-based tanh.
// last=0: in-place [T,B] (Xhi==Ohi). last=1: out row = b*TT + t.
// ---------------------------------------------------------------------------
__global__ __launch_bounds__(256)
void sru_scan(const float* __restrict__ Ux, const __half* __restrict__ Ufr,
              const float* __restrict__ b_l, const float* __restrict__ c0,
              const __half* __restrict__ Xhi, const __half* __restrict__ Xlo,
              __half* __restrict__ Ohi, __half* __restrict__ Olo,
              float* __restrict__ c_out, int last)
{
    int idx = blockIdx.x * blockDim.x + threadIdx.x;
    if (idx >= BB * HH) return;
    int j = idx & (HH - 1);
    int b = idx >> 10;

    float bf = b_l[j];
    float br = b_l[HH + j];
    float c  = c0[idx];

    // preload t = 0
    float xt = Ux[(size_t)b * HH + j];
    float fp = __half2float(Ufr[(size_t)b * (2 * HH) + j]);
    float rp = __half2float(Ufr[(size_t)b * (2 * HH) + HH + j]);
    size_t xi0 = (size_t)b * HH + j;
    float xinh = __half2float(Xhi[xi0]);
    float xinl = __half2float(Xlo[xi0]);

#pragma unroll
    for (int t = 0; t < TT; t++) {
        // prefetch t+1 before the serial compute chain
        float xt_n = 0.f, fp_n = 0.f, rp_n = 0.f, xinh_n = 0.f, xinl_n = 0.f;
        if (t + 1 < TT) {
            size_t m = (size_t)(t + 1) * BB + b;
            xt_n = Ux[m * HH + j];
            fp_n = __half2float(Ufr[m * (2 * HH) + j]);
            rp_n = __half2float(Ufr[m * (2 * HH) + HH + j]);
            xinh_n = __half2float(Xhi[m * HH + j]);
            xinl_n = __half2float(Xlo[m * HH + j]);
        }

        float f = 1.f / (1.f + __expf(-(fp + bf)));
        float r = 1.f / (1.f + __expf(-(rp + br)));
        c = f * c + (1.f - f) * xt;
        float e2 = __expf(2.f * c);
        float th = 1.f - 2.f / (e2 + 1.f);
        float xin_v = xinh + xinl;
        float hv = r * th + (1.f - r) * xin_v;

        size_t cur = ((size_t)t * BB + b) * HH + j;
        size_t oi = last ? ((size_t)(b * TT + t) * HH + j) : cur;
        __half hb, lb;
        split_h(hv, hb, lb);
        Ohi[oi] = hb;
        Olo[oi] = lb;

        xt = xt_n; fp = fp_n; rp = rp_n; xinh = xinh_n; xinl = xinl_n;
    }
    c_out[idx] = c;
}

// ---------------------------------------------------------------------------
// kernel_launch
// ---------------------------------------------------------------------------
extern "C" void kernel_launch(void* const* d_in, const int* in_sizes, int n_in,
                              void* d_out, int out_size)
{
    const float* x      = (const float*)d_in[0];
    const float* hidden = (const float*)d_in[1];
    const float* W1     = (const float*)d_in[2];
    const float* b1     = (const float*)d_in[3];
    const float* sru_W  = (const float*)d_in[4];
    const float* sru_b  = (const float*)d_in[5];
    const float* W3     = (const float*)d_in[6];
    const float* b3     = (const float*)d_in[7];
    const float* W4     = (const float*)d_in[8];
    const float* b4     = (const float*)d_in[9];

    float* out = (float*)d_out;
    float* logits_out = out;                          // [2560, 1095]
    float* fx_out     = out + (size_t)MM * NOUT;      // [2560, 1024]
    float* hid_out    = fx_out + (size_t)MM * HH;     // [12, 128, 1024]

    float* Ux;
    __half *Ufr, *Ahi, *Alo, *Bhi, *Blo, *Wt, *W3t, *W4t;
    cudaGetSymbolAddress((void**)&Ux, g_Ux);
    cudaGetSymbolAddress((void**)&Ufr, g_Ufr);
    cudaGetSymbolAddress((void**)&Ahi, g_Ahi);
    cudaGetSymbolAddress((void**)&Alo, g_Alo);
    cudaGetSymbolAddress((void**)&Bhi, g_Bhi);
    cudaGetSymbolAddress((void**)&Blo, g_Blo);
    cudaGetSymbolAddress((void**)&Wt, g_Wt);
    cudaGetSymbolAddress((void**)&W3t, g_W3t);
    cudaGetSymbolAddress((void**)&W4t, g_W4t);

    cudaFuncSetAttribute(gemm_mma, cudaFuncAttributeMaxDynamicSharedMemorySize, GSMEM);
    cudaFuncSetAttribute(gemm_sru, cudaFuncAttributeMaxDynamicSharedMemorySize, S_GSMEM);

    dim3 blk(256);

    // 0) all weight prep in one launch (fp16 truncation, K-major)
    transpose_all<<<dim3(N3H / 32, HH / 64, LL + 2), blk>>>(
        sru_W, W3, W4, Wt, W3t, W4t);

    // 1) dense1 (fp32): fp16 hi/lo split of x @ W1 + b1, [T,B] order
    sgemm_d1<<<dim3(HH / 128, MM / 128), blk>>>(x, W1, b1, Ahi, Alo, MM, HH, DIN);

    // 2) SRU layers: 128x128 tiles (halved B traffic); x_tilde 2-MMA -> Ux fp32,
    //    gates 1-MMA -> raw fp16 Ufr
    for (int l = 0; l < LL; l++) {
        gemm_sru<<<dim3(N3H / 128, MM / 128), blk, S_GSMEM>>>(
            Ahi, Alo, Wt + (size_t)l * N3H * HH, Ux, Ufr);
        int last = (l == LL - 1);
        sru_scan<<<(BB * HH) / 256, blk>>>(
            Ux, Ufr, sru_b + (size_t)l * 2 * HH, hidden + (size_t)l * BB * HH,
            Ahi, Alo,
            last ? Bhi : Ahi, last ? Blo : Alo,
            hid_out + (size_t)l * BB * HH, last);
    }

    // 3) fx = h([B,T]) @ W3 + b3, with fused relu+split into Ahi/Alo
    gemm_mma<<<dim3(HH / 128, MM / 64), blk, GSMEM>>>(
        Bhi, Blo, W3t, b3, fx_out, HH, Ahi, Alo);

    // 4) logits = relu(fx) @ W4 + b4
    gemm_mma<<<dim3(NPAD4 / 128, MM / 64), blk, GSMEM>>>(
        Ahi, Alo, W4t, b4, logits_out, NOUT, nullptr, nullptr);
}

// round 16
// speedup vs baseline: 1.1472x; 1.1472x over previous
#include <cuda_runtime.h>
#include <cuda_fp16.h>
#include <cstdint>
#include <math.h>

// Problem constants
#define BB   128
#define TT   20
#define DIN  200
#define HH   1024
#define LL   12
#define NOUT 1095
#define MM   (BB * TT)      // 2560
#define N3H  (3 * HH)       // 3072
#define NPAD4 1152          // W4 N padded to multiple of 128
#define K1P  256            // dense1 K padded

// ---------------------------------------------------------------------------
// Scratch (device globals)
// ---------------------------------------------------------------------------
__device__ float g_Ux[MM * HH];           // x_tilde (fp32)
__device__ __half g_Ufr[MM * 2 * HH];     // gate pre-activations (fp16 raw)
__device__ __half g_Ahi[MM * HH];     // activations [T,B] order, fp16 hi
__device__ __half g_Alo[MM * HH];     // fp16 lo (residual)
__device__ __half g_Bhi[MM * HH];     // last-layer output, [B,T] order
__device__ __half g_Blo[MM * HH];
__device__ __half g_Wt[LL * N3H * HH];   // weights fp16 (truncated), K-major
__device__ __half g_W3t[HH * HH];
__device__ __half g_W4t[NPAD4 * HH];
__device__ __half g_Xh[MM * K1P];         // dense1 input hi, [T,B] order, K=256
__device__ __half g_Xl[MM * K1P];
__device__ __half g_W1h[HH * K1P];        // W1^T hi/lo, K-major 256-pad
__device__ __half g_W1l[HH * K1P];

// ---------------------------------------------------------------------------
// Helpers (base-ISA: cp.async, ldmatrix, mma.sync)
// ---------------------------------------------------------------------------
__device__ __forceinline__ uint32_t smem_u32(const void* p) {
    uint32_t a;
    asm("{ .reg .u64 t; cvta.to.shared.u64 t, %1; cvt.u32.u64 %0, t; }"
        : "=r"(a) : "l"(p));
    return a;
}

#define SWZ128(o) ((o) ^ (((o) >> 3) & 0x70))

__device__ __forceinline__ void cp_async16(uint32_t dst, const void* src) {
    asm volatile("cp.async.cg.shared.global [%0], [%1], 16;" :: "r"(dst), "l"(src));
}
__device__ __forceinline__ void cp_commit() {
    asm volatile("cp.async.commit_group;" ::: "memory");
}
__device__ __forceinline__ void cp_wait1() {
    asm volatile("cp.async.wait_group 1;" ::: "memory");
}

__device__ __forceinline__ void ldsm_x4(uint32_t* r, uint32_t addr) {
    asm volatile("ldmatrix.sync.aligned.m8n8.x4.shared.b16 {%0,%1,%2,%3}, [%4];"
                 : "=r"(r[0]), "=r"(r[1]), "=r"(r[2]), "=r"(r[3]) : "r"(addr));
}

__device__ __forceinline__ void mma_f16(float* d, const uint32_t* a, const uint32_t* b) {
    asm volatile(
        "mma.sync.aligned.m16n8k16.row.col.f32.f16.f16.f32 "
        "{%0,%1,%2,%3}, {%4,%5,%6,%7}, {%8,%9}, {%0,%1,%2,%3};"
        : "+f"(d[0]), "+f"(d[1]), "+f"(d[2]), "+f"(d[3])
        : "r"(a[0]), "r"(a[1]), "r"(a[2]), "r"(a[3]), "r"(b[0]), "r"(b[1]));
}

__device__ __forceinline__ void split_h(float v, __half& hi, __half& lo) {
    hi = __float2half_rn(v);
    lo = __float2half_rn(v - __half2float(hi));
}

// ---------------------------------------------------------------------------
// fp16 GEMM, templated on K (GKT) and THREE (exact 3-MMA with B hi/lo).
// BM=64, BN=128, BK=64, NSTAGE=3. GKT=1024,THREE=false: r14-proven config
// (96KB smem -> 2 CTAs/SM). GKT=256,THREE=true: dense1 (exact hi/lo x hi/lo).
// Columns < n2_split: 2-MMA hi/lo A split; else hi-only 1-MMA (SRU gates).
// Output modes:
//   Ux != nullptr (SRU): cols < HH -> fp32 Ux; cols >= HH -> raw fp16 Ufr.
//   else: optional C (+bias), optional split(relu?) to Ohi/Olo.
// ---------------------------------------------------------------------------
#define TILE_AH 8192               // 64 rows x 64 k x 2B (one A half)
#define TILE_BB 16384              // 128 rows x 64 k x 2B
#define NSTAGE  3

template<int GKT, bool THREE>
__device__ __forceinline__ void g_load_stage(
    uint32_t sbase, int st, int k0, int tid, int bm, int bn, bool loadLo,
    const __half* __restrict__ Ahi, const __half* __restrict__ Alo,
    const __half* __restrict__ Bh, const __half* __restrict__ Bl)
{
    constexpr int STAGE = 2 * TILE_AH + (THREE ? 2 : 1) * TILE_BB;
    uint32_t base = sbase + (st % NSTAGE) * STAGE;
#pragma unroll
    for (int p = 0; p < 2; p++) {              // A: 64 rows x 8 chunks = 512
        int idx = tid + p * 256;
        int row = idx >> 3, ch = idx & 7;
        uint32_t off = SWZ128((uint32_t)(row * 128 + ch * 16));
        size_t ga = (size_t)(bm + row) * GKT + k0 + ch * 8;
        cp_async16(base + off, Ahi + ga);
        if (loadLo) cp_async16(base + TILE_AH + off, Alo + ga);
    }
#pragma unroll
    for (int p = 0; p < 4; p++) {              // B: 128 rows x 8 chunks = 1024
        int idx = tid + p * 256;
        int row = idx >> 3, ch = idx & 7;
        uint32_t off = SWZ128((uint32_t)(row * 128 + ch * 16));
        size_t gb = (size_t)(bn + row) * GKT + k0 + ch * 8;
        cp_async16(base + 2 * TILE_AH + off, Bh + gb);
        if (THREE) cp_async16(base + 2 * TILE_AH + TILE_BB + off, Bl + gb);
    }
}

template<int GKT, bool THREE>
__global__ __launch_bounds__(256, 2)
void gemm_mma(const __half* __restrict__ Ahi, const __half* __restrict__ Alo,
              const __half* __restrict__ Bh, const __half* __restrict__ Bl,
              const float* __restrict__ bias, float* __restrict__ C, int Nact,
              int n2_split, int do_relu,
              __half* __restrict__ Ohi, __half* __restrict__ Olo,
              float* __restrict__ Ux, __half* __restrict__ Ufr)
{
    constexpr int STAGE = 2 * TILE_AH + (THREE ? 2 : 1) * TILE_BB;
    constexpr int KST = GKT / 64;
    extern __shared__ char smem[];
    const uint32_t sbase = smem_u32(smem);
    const int tid = threadIdx.x;
    const int wid = tid >> 5, lane = tid & 31;
    const int warp_m = wid & 1, warp_n = wid >> 1;   // 2 x 4, warp tile 32x32
    const int bm = blockIdx.y * 64;
    const int bn = blockIdx.x * 128;
    const bool useLo = (bn < n2_split);   // uniform per CTA (n2_split % 128 == 0)

    float acc[2][4][4];
#pragma unroll
    for (int i = 0; i < 2; i++)
#pragma unroll
        for (int j = 0; j < 4; j++)
#pragma unroll
            for (int q = 0; q < 4; q++) acc[i][j][q] = 0.f;

    // prologue: 2 stages in flight
    g_load_stage<GKT, THREE>(sbase, 0, 0, tid, bm, bn, useLo, Ahi, Alo, Bh, Bl);
    cp_commit();
    g_load_stage<GKT, THREE>(sbase, 1, 64, tid, bm, bn, useLo, Ahi, Alo, Bh, Bl);
    cp_commit();

    const int a_r = (lane & 7) + ((lane >> 3) & 1) * 8;
    const int a_c = (lane >> 4);
    const int b_r = (lane & 7) + ((lane >> 4) & 1) * 8;
    const int b_c = (lane >> 3) & 1;

    for (int s = 0; s < KST; s++) {
        cp_wait1();          // stage s ready (stage s+1 may still be in flight)
        __syncthreads();     // all warps done reading stage s-1

        if (s + 2 < KST) {
            g_load_stage<GKT, THREE>(sbase, s + 2, (s + 2) * 64, tid, bm, bn,
                                     useLo, Ahi, Alo, Bh, Bl);
        }
        cp_commit();         // uniform group count (empty in tail)

        uint32_t stg = sbase + (s % NSTAGE) * STAGE;
#pragma unroll
        for (int h = 0; h < 4; h++) {       // four k16 chunks of BK=64
            uint32_t a_hi[2][4], a_lo[2][4], b_h[2][4], b_l[2][4];
#pragma unroll
            for (int mt = 0; mt < 2; mt++) {
                int row = warp_m * 32 + mt * 16 + a_r;
                uint32_t off = SWZ128((uint32_t)(row * 128 + h * 32 + a_c * 16));
                ldsm_x4(a_hi[mt], stg + off);
                if (useLo) ldsm_x4(a_lo[mt], stg + TILE_AH + off);
            }
#pragma unroll
            for (int p = 0; p < 2; p++) {
                int row = warp_n * 32 + p * 16 + b_r;
                uint32_t off = SWZ128((uint32_t)(row * 128 + h * 32 + b_c * 16));
                ldsm_x4(b_h[p], stg + 2 * TILE_AH + off);
                if (THREE) ldsm_x4(b_l[p], stg + 2 * TILE_AH + TILE_BB + off);
            }
#pragma unroll
            for (int mt = 0; mt < 2; mt++)
#pragma unroll
                for (int p = 0; p < 2; p++)
#pragma unroll
                    for (int q = 0; q < 2; q++) {
                        float* d = acc[mt][2 * p + q];
                        mma_f16(d, a_hi[mt], &b_h[p][2 * q]);
                        if (useLo) mma_f16(d, a_lo[mt], &b_h[p][2 * q]);
                        if (THREE) mma_f16(d, a_hi[mt], &b_l[p][2 * q]);
                    }
        }
    }

    // epilogue
    const int er = lane >> 2;
    const int ec = (lane & 3) * 2;
    const bool sru_mode = (Ux != nullptr);
    const bool even_stride = (Nact & 1) == 0;
#pragma unroll
    for (int mt = 0; mt < 2; mt++) {
#pragma unroll
        for (int nt = 0; nt < 4; nt++) {
            int row = bm + warp_m * 32 + mt * 16 + er;
            int col = bn + warp_n * 32 + nt * 8 + ec;
            float* d = acc[mt][nt];
            if (sru_mode) {
                if (col < HH) {
                    *(float2*)(Ux + (size_t)row * HH + col) = make_float2(d[0], d[1]);
                    *(float2*)(Ux + (size_t)(row + 8) * HH + col) = make_float2(d[2], d[3]);
                } else {
                    int cg = col - HH;
                    *(__half2*)(Ufr + (size_t)row * (2 * HH) + cg) =
                        __halves2half2(__float2half_rn(d[0]), __float2half_rn(d[1]));
                    *(__half2*)(Ufr + (size_t)(row + 8) * (2 * HH) + cg) =
                        __halves2half2(__float2half_rn(d[2]), __float2half_rn(d[3]));
                }
            } else {
                float b0 = bias ? bias[col] : 0.f;
                float b1 = (bias && col + 1 < Nact) ? bias[col + 1] : 0.f;
                float v00 = d[0] + b0, v01 = d[1] + b1;
                float v10 = d[2] + b0, v11 = d[3] + b1;
                if (C) {
                    if (even_stride) {
                        *(float2*)(C + (size_t)row * Nact + col) = make_float2(v00, v01);
                        *(float2*)(C + (size_t)(row + 8) * Nact + col) = make_float2(v10, v11);
                    } else {
                        if (col < Nact) {
                            C[(size_t)row * Nact + col]       = v00;
                            C[(size_t)(row + 8) * Nact + col] = v10;
                        }
                        if (col + 1 < Nact) {
                            C[(size_t)row * Nact + col + 1]       = v01;
                            C[(size_t)(row + 8) * Nact + col + 1] = v11;
                        }
                    }
                }
                if (Ohi) {   // split (optionally relu'd); Nact even here
                    float r00 = do_relu ? fmaxf(v00, 0.f) : v00;
                    float r01 = do_relu ? fmaxf(v01, 0.f) : v01;
                    float r10 = do_relu ? fmaxf(v10, 0.f) : v10;
                    float r11 = do_relu ? fmaxf(v11, 0.f) : v11;
                    __half h00, l00, h01, l01, h10, l10, h11, l11;
                    split_h(r00, h00, l00); split_h(r01, h01, l01);
                    split_h(r10, h10, l10); split_h(r11, h11, l11);
                    size_t i0 = (size_t)row * Nact + col;
                    size_t i1 = (size_t)(row + 8) * Nact + col;
                    *(__half2*)(Ohi + i0) = __halves2half2(h00, h01);
                    *(__half2*)(Ohi + i1) = __halves2half2(h10, h11);
                    *(__half2*)(Olo + i0) = __halves2half2(l00, l01);
                    *(__half2*)(Olo + i1) = __halves2half2(l10, l11);
                }
            }
        }
    }
}

// ---------------------------------------------------------------------------
// All big weight transposes in ONE launch. z: 0..11 SRU, 12 W3, 13 W4.
// ---------------------------------------------------------------------------
__global__ __launch_bounds__(256)
void transpose_all(const float* __restrict__ sru_W,
                   const float* __restrict__ W3,
                   const float* __restrict__ W4,
                   __half* __restrict__ Wt,
                   __half* __restrict__ W3t,
                   __half* __restrict__ W4t)
{
    int z = blockIdx.z;
    const float* W;
    __half* hi;
    int Nsrc, Npad;
    if (z < LL) {
        W = sru_W + (size_t)z * HH * N3H;
        hi = Wt + (size_t)z * N3H * HH;
        Nsrc = N3H; Npad = N3H;
    } else if (z == LL) {
        W = W3; hi = W3t; Nsrc = HH; Npad = HH;
    } else {
        W = W4; hi = W4t; Nsrc = NOUT; Npad = NPAD4;
    }

    int nb = blockIdx.x * 32, kb = blockIdx.y * 64;
    if (nb >= Npad) return;

    __shared__ float t[64][33];
    int tx = threadIdx.x & 31;
    int ty = threadIdx.x >> 5;
    int n = nb + tx;
#pragma unroll
    for (int i = 0; i < 8; i++) {
        int kk = ty * 8 + i;
        t[kk][tx] = (n < Nsrc) ? W[(size_t)(kb + kk) * Nsrc + n] : 0.f;
    }
    __syncthreads();
#pragma unroll
    for (int p = 0; p < 4; p++) {
        int idx = threadIdx.x + p * 256;
        int nl = idx >> 5, kp = idx & 31;
        float v0 = t[2 * kp][nl];
        float v1 = t[2 * kp + 1][nl];
        size_t o = ((size_t)(nb + nl) * HH + kb) / 2 + kp;
        ((__half2*)hi)[o] = __halves2half2(__float2half_rn(v0), __float2half_rn(v1));
    }
}

// ---------------------------------------------------------------------------
// W1 [200,1024] -> W1h/W1l [1024 n][256 k] (hi/lo, zero-padded k>=200)
// ---------------------------------------------------------------------------
__global__ __launch_bounds__(256)
void w1_prep(const float* __restrict__ W1,
             __half* __restrict__ W1h, __half* __restrict__ W1l)
{
    int nb = blockIdx.x * 32, kb = blockIdx.y * 64;
    __shared__ float t[64][33];
    int tx = threadIdx.x & 31;
    int ty = threadIdx.x >> 5;
    int n = nb + tx;
#pragma unroll
    for (int i = 0; i < 8; i++) {
        int kk = kb + ty * 8 + i;
        t[ty * 8 + i][tx] = (kk < DIN) ? W1[(size_t)kk * HH + n] : 0.f;
    }
    __syncthreads();
#pragma unroll
    for (int p = 0; p < 4; p++) {
        int idx = threadIdx.x + p * 256;
        int nl = idx >> 5, kp = idx & 31;
        float v0 = t[2 * kp][nl];
        float v1 = t[2 * kp + 1][nl];
        __half h0, l0, h1, l1;
        split_h(v0, h0, l0);
        split_h(v1, h1, l1);
        size_t o = ((size_t)(nb + nl) * K1P + kb) / 2 + kp;
        ((__half2*)W1h)[o] = __halves2half2(h0, h1);
        ((__half2*)W1l)[o] = __halves2half2(l0, l1);
    }
}

// ---------------------------------------------------------------------------
// x [B,T,200] -> Xh/Xl [m=t*BB+b][256] hi/lo (zero-padded k>=200)
// ---------------------------------------------------------------------------
__global__ __launch_bounds__(256)
void x_prep(const float* __restrict__ x,
            __half* __restrict__ Xh, __half* __restrict__ Xl)
{
    int i = blockIdx.x * blockDim.x + threadIdx.x;
    if (i >= MM * K1P) return;
    int m = i >> 8, k = i & (K1P - 1);
    int b = m & (BB - 1), t = m >> 7;
    float v = (k < DIN) ? x[(size_t)(b * TT + t) * DIN + k] : 0.f;
    __half h, l;
    split_h(v, h, l);
    Xh[i] = h;
    Xl[i] = l;
}

// ---------------------------------------------------------------------------
// SRU scan (r14): x_tilde fp32 Ux, gate pre-acts fp16 Ufr. Bias+sigmoid here.
// Software prefetch, __expf tanh. last=1: out row = b*TT + t.
// ---------------------------------------------------------------------------
__global__ __launch_bounds__(256)
void sru_scan(const float* __restrict__ Ux, const __half* __restrict__ Ufr,
              const float* __restrict__ b_l, const float* __restrict__ c0,
              const __half* __restrict__ Xhi, const __half* __restrict__ Xlo,
              __half* __restrict__ Ohi, __half* __restrict__ Olo,
              float* __restrict__ c_out, int last)
{
    int idx = blockIdx.x * blockDim.x + threadIdx.x;
    if (idx >= BB * HH) return;
    int j = idx & (HH - 1);
    int b = idx >> 10;

    float bf = b_l[j];
    float br = b_l[HH + j];
    float c  = c0[idx];

    float xt = Ux[(size_t)b * HH + j];
    float fp = __half2float(Ufr[(size_t)b * (2 * HH) + j]);
    float rp = __half2float(Ufr[(size_t)b * (2 * HH) + HH + j]);
    size_t xi0 = (size_t)b * HH + j;
    float xinh = __half2float(Xhi[xi0]);
    float xinl = __half2float(Xlo[xi0]);

#pragma unroll
    for (int t = 0; t < TT; t++) {
        float xt_n = 0.f, fp_n = 0.f, rp_n = 0.f, xinh_n = 0.f, xinl_n = 0.f;
        if (t + 1 < TT) {
            size_t m = (size_t)(t + 1) * BB + b;
            xt_n = Ux[m * HH + j];
            fp_n = __half2float(Ufr[m * (2 * HH) + j]);
            rp_n = __half2float(Ufr[m * (2 * HH) + HH + j]);
            xinh_n = __half2float(Xhi[m * HH + j]);
            xinl_n = __half2float(Xlo[m * HH + j]);
        }

        float f = 1.f / (1.f + __expf(-(fp + bf)));
        float r = 1.f / (1.f + __expf(-(rp + br)));
        c = f * c + (1.f - f) * xt;
        float e2 = __expf(2.f * c);
        float th = 1.f - 2.f / (e2 + 1.f);
        float xin_v = xinh + xinl;
        float hv = r * th + (1.f - r) * xin_v;

        size_t cur = ((size_t)t * BB + b) * HH + j;
        size_t oi = last ? ((size_t)(b * TT + t) * HH + j) : cur;
        __half hb, lb;
        split_h(hv, hb, lb);
        Ohi[oi] = hb;
        Olo[oi] = lb;

        xt = xt_n; fp = fp_n; rp = rp_n; xinh = xinh_n; xinl = xinl_n;
    }
    c_out[idx] = c;
}

// ---------------------------------------------------------------------------
// kernel_launch
// ---------------------------------------------------------------------------
extern "C" void kernel_launch(void* const* d_in, const int* in_sizes, int n_in,
                              void* d_out, int out_size)
{
    const float* x      = (const float*)d_in[0];
    const float* hidden = (const float*)d_in[1];
    const float* W1     = (const float*)d_in[2];
    const float* b1     = (const float*)d_in[3];
    const float* sru_W  = (const float*)d_in[4];
    const float* sru_b  = (const float*)d_in[5];
    const float* W3     = (const float*)d_in[6];
    const float* b3     = (const float*)d_in[7];
    const float* W4     = (const float*)d_in[8];
    const float* b4     = (const float*)d_in[9];

    float* out = (float*)d_out;
    float* logits_out = out;                          // [2560, 1095]
    float* fx_out     = out + (size_t)MM * NOUT;      // [2560, 1024]
    float* hid_out    = fx_out + (size_t)MM * HH;     // [12, 128, 1024]

    float* Ux;
    __half *Ufr, *Ahi, *Alo, *Bhi, *Blo, *Wt, *W3t, *W4t, *Xh, *Xl, *W1h, *W1l;
    cudaGetSymbolAddress((void**)&Ux, g_Ux);
    cudaGetSymbolAddress((void**)&Ufr, g_Ufr);
    cudaGetSymbolAddress((void**)&Ahi, g_Ahi);
    cudaGetSymbolAddress((void**)&Alo, g_Alo);
    cudaGetSymbolAddress((void**)&Bhi, g_Bhi);
    cudaGetSymbolAddress((void**)&Blo, g_Blo);
    cudaGetSymbolAddress((void**)&Wt, g_Wt);
    cudaGetSymbolAddress((void**)&W3t, g_W3t);
    cudaGetSymbolAddress((void**)&W4t, g_W4t);
    cudaGetSymbolAddress((void**)&Xh, g_Xh);
    cudaGetSymbolAddress((void**)&Xl, g_Xl);
    cudaGetSymbolAddress((void**)&W1h, g_W1h);
    cudaGetSymbolAddress((void**)&W1l, g_W1l);

    const int SM2 = NSTAGE * (2 * TILE_AH + TILE_BB);      // 98304
    const int SM3 = NSTAGE * (2 * TILE_AH + 2 * TILE_BB);  // 147456
    cudaFuncSetAttribute(gemm_mma<HH, false>,
                         cudaFuncAttributeMaxDynamicSharedMemorySize, SM2);
    cudaFuncSetAttribute(gemm_mma<K1P, true>,
                         cudaFuncAttributeMaxDynamicSharedMemorySize, SM3);

    dim3 blk(256);
    const int NO_SPLIT = 1 << 30;

    // 0) weight/input prep
    transpose_all<<<dim3(N3H / 32, HH / 64, LL + 2), blk>>>(
        sru_W, W3, W4, Wt, W3t, W4t);
    w1_prep<<<dim3(HH / 32, K1P / 64), blk>>>(W1, W1h, W1l);
    x_prep<<<(MM * K1P) / 256, blk>>>(x, Xh, Xl);

    // 1) dense1 (exact 3-MMA fp16): split(x @ W1 + b1) -> Ahi/Alo, [T,B] order
    gemm_mma<K1P, true><<<dim3(HH / 128, MM / 64), blk, SM3>>>(
        Xh, Xl, W1h, W1l, b1, nullptr, HH, NO_SPLIT, 0,
        Ahi, Alo, nullptr, nullptr);

    // 2) SRU layers: x_tilde (<1024) 2-MMA -> Ux fp32; gates 1-MMA -> fp16 raw
    for (int l = 0; l < LL; l++) {
        gemm_mma<HH, false><<<dim3(N3H / 128, MM / 64), blk, SM2>>>(
            Ahi, Alo, Wt + (size_t)l * N3H * HH, nullptr,
            nullptr, nullptr, N3H, HH, 0, nullptr, nullptr,
            Ux, Ufr);
        int last = (l == LL - 1);
        sru_scan<<<(BB * HH) / 256, blk>>>(
            Ux, Ufr, sru_b + (size_t)l * 2 * HH, hidden + (size_t)l * BB * HH,
            Ahi, Alo,
            last ? Bhi : Ahi, last ? Blo : Alo,
            hid_out + (size_t)l * BB * HH, last);
    }

    // 3) fx = h([B,T]) @ W3 + b3, fused relu+split into Ahi/Alo
    gemm_mma<HH, false><<<dim3(HH / 128, MM / 64), blk, SM2>>>(
        Bhi, Blo, W3t, nullptr, b3, fx_out, HH, NO_SPLIT, 1,
        Ahi, Alo, nullptr, nullptr);

    // 4) logits = relu(fx) @ W4 + b4
    gemm_mma<HH, false><<<dim3(NPAD4 / 128, MM / 64), blk, SM2>>>(
        Ahi, Alo, W4t, nullptr, b4, logits_out, NOUT, NO_SPLIT, 0,
        nullptr, nullptr, nullptr, nullptr);
}

// round 17
// speedup vs baseline: 1.1611x; 1.0121x over previous
#include <cuda_runtime.h>
#include <cuda_fp16.h>
#include <cstdint>
#include <math.h>

// Problem constants
#define BB   128
#define TT   20
#define DIN  200
#define HH   1024
#define LL   12
#define NOUT 1095
#define MM   (BB * TT)      // 2560
#define N3H  (3 * HH)       // 3072
#define NPAD4 1152          // W4 N padded to multiple of 128
#define K1P  256            // dense1 K padded

// ---------------------------------------------------------------------------
// Scratch (device globals)
// ---------------------------------------------------------------------------
__device__ float g_Ux[MM * HH];           // x_tilde (fp32)
__device__ __half g_Ufr[MM * 2 * HH];     // gate pre-activations (fp16 raw)
__device__ __half g_Ahi[MM * HH];     // activations [T,B] order, fp16 hi
__device__ __half g_Alo[MM * HH];     // fp16 lo (residual)
__device__ __half g_Bhi[MM * HH];     // last-layer output, [B,T] order
__device__ __half g_Blo[MM * HH];
__device__ __half g_Wt[LL * N3H * HH];   // weights fp16 (truncated), K-major
__device__ __half g_W3t[HH * HH];
__device__ __half g_W4t[NPAD4 * HH];
__device__ __half g_Xh[MM * K1P];         // dense1 input hi, [T,B] order, K=256
__device__ __half g_Xl[MM * K1P];
__device__ __half g_W1h[HH * K1P];        // W1^T hi/lo, K-major 256-pad
__device__ __half g_W1l[HH * K1P];

// ---------------------------------------------------------------------------
// Helpers (base-ISA: cp.async, ldmatrix, mma.sync)
// ---------------------------------------------------------------------------
__device__ __forceinline__ uint32_t smem_u32(const void* p) {
    uint32_t a;
    asm("{ .reg .u64 t; cvta.to.shared.u64 t, %1; cvt.u32.u64 %0, t; }"
        : "=r"(a) : "l"(p));
    return a;
}

#define SWZ128(o) ((o) ^ (((o) >> 3) & 0x70))

__device__ __forceinline__ void cp_async16(uint32_t dst, const void* src) {
    asm volatile("cp.async.cg.shared.global [%0], [%1], 16;" :: "r"(dst), "l"(src));
}
__device__ __forceinline__ void cp_commit() {
    asm volatile("cp.async.commit_group;" ::: "memory");
}
__device__ __forceinline__ void cp_wait1() {
    asm volatile("cp.async.wait_group 1;" ::: "memory");
}

__device__ __forceinline__ void ldsm_x4(uint32_t* r, uint32_t addr) {
    asm volatile("ldmatrix.sync.aligned.m8n8.x4.shared.b16 {%0,%1,%2,%3}, [%4];"
                 : "=r"(r[0]), "=r"(r[1]), "=r"(r[2]), "=r"(r[3]) : "r"(addr));
}

__device__ __forceinline__ void mma_f16(float* d, const uint32_t* a, const uint32_t* b) {
    asm volatile(
        "mma.sync.aligned.m16n8k16.row.col.f32.f16.f16.f32 "
        "{%0,%1,%2,%3}, {%4,%5,%6,%7}, {%8,%9}, {%0,%1,%2,%3};"
        : "+f"(d[0]), "+f"(d[1]), "+f"(d[2]), "+f"(d[3])
        : "r"(a[0]), "r"(a[1]), "r"(a[2]), "r"(a[3]), "r"(b[0]), "r"(b[1]));
}

__device__ __forceinline__ void split_h(float v, __half& hi, __half& lo) {
    hi = __float2half_rn(v);
    lo = __float2half_rn(v - __half2float(hi));
}

// ---------------------------------------------------------------------------
// fp16 GEMM, templated on K (GKT), THREE (exact 3-MMA, B hi/lo), and BNT.
// BM=64, BK=64, NSTAGE=3. <1024,false,128>: r14/16-proven SRU/fx/logits config
// (96KB smem -> 2 CTAs/SM). <256,true,64>: dense1 (96KB -> 2 CTAs/SM too).
// Columns < n2_split: 2-MMA hi/lo A split; else hi-only 1-MMA (SRU gates).
// Output modes:
//   Ux != nullptr (SRU): cols < HH -> fp32 Ux; cols >= HH -> raw fp16 Ufr.
//   else: optional C (+bias), optional split(relu?) to Ohi/Olo.
// ---------------------------------------------------------------------------
#define TILE_AH 8192               // 64 rows x 64 k x 2B (one A half)
#define NSTAGE  3

template<int GKT, bool THREE, int BNT>
__device__ __forceinline__ void g_load_stage(
    uint32_t sbase, int st, int k0, int tid, int bm, int bn, bool loadLo,
    const __half* __restrict__ Ahi, const __half* __restrict__ Alo,
    const __half* __restrict__ Bh, const __half* __restrict__ Bl)
{
    constexpr int TILE_BT = BNT * 128;  // BNT rows x 64 k x 2B
    constexpr int STAGE = 2 * TILE_AH + (THREE ? 2 : 1) * TILE_BT;
    uint32_t base = sbase + (st % NSTAGE) * STAGE;
#pragma unroll
    for (int p = 0; p < 2; p++) {              // A: 64 rows x 8 chunks = 512
        int idx = tid + p * 256;
        int row = idx >> 3, ch = idx & 7;
        uint32_t off = SWZ128((uint32_t)(row * 128 + ch * 16));
        size_t ga = (size_t)(bm + row) * GKT + k0 + ch * 8;
        cp_async16(base + off, Ahi + ga);
        if (loadLo) cp_async16(base + TILE_AH + off, Alo + ga);
    }
#pragma unroll
    for (int p = 0; p < BNT / 32; p++) {       // B: BNT rows x 8 chunks
        int idx = tid + p * 256;
        int row = idx >> 3, ch = idx & 7;
        uint32_t off = SWZ128((uint32_t)(row * 128 + ch * 16));
        size_t gb = (size_t)(bn + row) * GKT + k0 + ch * 8;
        cp_async16(base + 2 * TILE_AH + off, Bh + gb);
        if (THREE) cp_async16(base + 2 * TILE_AH + TILE_BT + off, Bl + gb);
    }
}

template<int GKT, bool THREE, int BNT>
__global__ __launch_bounds__(256, 2)
void gemm_mma(const __half* __restrict__ Ahi, const __half* __restrict__ Alo,
              const __half* __restrict__ Bh, const __half* __restrict__ Bl,
              const float* __restrict__ bias, float* __restrict__ C, int Nact,
              int n2_split, int do_relu,
              __half* __restrict__ Ohi, __half* __restrict__ Olo,
              float* __restrict__ Ux, __half* __restrict__ Ufr)
{
    constexpr int TILE_BT = BNT * 128;
    constexpr int STAGE = 2 * TILE_AH + (THREE ? 2 : 1) * TILE_BT;
    constexpr int KST = GKT / 64;
    constexpr int WP  = BNT / 64;      // b-frag tiles per warp
    constexpr int WTN = BNT / 4;       // warp tile n
    extern __shared__ char smem[];
    const uint32_t sbase = smem_u32(smem);
    const int tid = threadIdx.x;
    const int wid = tid >> 5, lane = tid & 31;
    const int warp_m = wid & 1, warp_n = wid >> 1;   // 2 x 4
    const int bm = blockIdx.y * 64;
    const int bn = blockIdx.x * BNT;
    const bool useLo = (bn < n2_split);

    float acc[2][2 * WP][4];
#pragma unroll
    for (int i = 0; i < 2; i++)
#pragma unroll
        for (int j = 0; j < 2 * WP; j++)
#pragma unroll
            for (int q = 0; q < 4; q++) acc[i][j][q] = 0.f;

    // prologue: 2 stages in flight
    g_load_stage<GKT, THREE, BNT>(sbase, 0, 0, tid, bm, bn, useLo, Ahi, Alo, Bh, Bl);
    cp_commit();
    g_load_stage<GKT, THREE, BNT>(sbase, 1, 64, tid, bm, bn, useLo, Ahi, Alo, Bh, Bl);
    cp_commit();

    const int a_r = (lane & 7) + ((lane >> 3) & 1) * 8;
    const int a_c = (lane >> 4);
    const int b_r = (lane & 7) + ((lane >> 4) & 1) * 8;
    const int b_c = (lane >> 3) & 1;

    for (int s = 0; s < KST; s++) {
        cp_wait1();          // stage s ready (stage s+1 may still be in flight)
        __syncthreads();     // all warps done reading stage s-1

        if (s + 2 < KST) {
            g_load_stage<GKT, THREE, BNT>(sbase, s + 2, (s + 2) * 64, tid, bm, bn,
                                          useLo, Ahi, Alo, Bh, Bl);
        }
        cp_commit();         // uniform group count (empty in tail)

        uint32_t stg = sbase + (s % NSTAGE) * STAGE;
#pragma unroll
        for (int h = 0; h < 4; h++) {       // four k16 chunks of BK=64
            uint32_t a_hi[2][4], a_lo[2][4], b_h[WP][4], b_l[WP][4];
#pragma unroll
            for (int mt = 0; mt < 2; mt++) {
                int row = warp_m * 32 + mt * 16 + a_r;
                uint32_t off = SWZ128((uint32_t)(row * 128 + h * 32 + a_c * 16));
                ldsm_x4(a_hi[mt], stg + off);
                if (useLo) ldsm_x4(a_lo[mt], stg + TILE_AH + off);
            }
#pragma unroll
            for (int p = 0; p < WP; p++) {
                int row = warp_n * WTN + p * 16 + b_r;
                uint32_t off = SWZ128((uint32_t)(row * 128 + h * 32 + b_c * 16));
                ldsm_x4(b_h[p], stg + 2 * TILE_AH + off);
                if (THREE) ldsm_x4(b_l[p], stg + 2 * TILE_AH + TILE_BT + off);
            }
#pragma unroll
            for (int mt = 0; mt < 2; mt++)
#pragma unroll
                for (int p = 0; p < WP; p++)
#pragma unroll
                    for (int q = 0; q < 2; q++) {
                        float* d = acc[mt][2 * p + q];
                        mma_f16(d, a_hi[mt], &b_h[p][2 * q]);
                        if (useLo) mma_f16(d, a_lo[mt], &b_h[p][2 * q]);
                        if (THREE) mma_f16(d, a_hi[mt], &b_l[p][2 * q]);
                    }
        }
    }

    // epilogue
    const int er = lane >> 2;
    const int ec = (lane & 3) * 2;
    const bool sru_mode = (Ux != nullptr);
    const bool even_stride = (Nact & 1) == 0;
#pragma unroll
    for (int mt = 0; mt < 2; mt++) {
#pragma unroll
        for (int nt = 0; nt < 2 * WP; nt++) {
            int row = bm + warp_m * 32 + mt * 16 + er;
            int col = bn + warp_n * WTN + nt * 8 + ec;
            float* d = acc[mt][nt];
            if (sru_mode) {
                if (col < HH) {
                    *(float2*)(Ux + (size_t)row * HH + col) = make_float2(d[0], d[1]);
                    *(float2*)(Ux + (size_t)(row + 8) * HH + col) = make_float2(d[2], d[3]);
                } else {
                    int cg = col - HH;
                    *(__half2*)(Ufr + (size_t)row * (2 * HH) + cg) =
                        __halves2half2(__float2half_rn(d[0]), __float2half_rn(d[1]));
                    *(__half2*)(Ufr + (size_t)(row + 8) * (2 * HH) + cg) =
                        __halves2half2(__float2half_rn(d[2]), __float2half_rn(d[3]));
                }
            } else {
                float b0 = bias ? bias[col] : 0.f;
                float b1 = (bias && col + 1 < Nact) ? bias[col + 1] : 0.f;
                float v00 = d[0] + b0, v01 = d[1] + b1;
                float v10 = d[2] + b0, v11 = d[3] + b1;
                if (C) {
                    if (even_stride) {
                        *(float2*)(C + (size_t)row * Nact + col) = make_float2(v00, v01);
                        *(float2*)(C + (size_t)(row + 8) * Nact + col) = make_float2(v10, v11);
                    } else {
                        if (col < Nact) {
                            C[(size_t)row * Nact + col]       = v00;
                            C[(size_t)(row + 8) * Nact + col] = v10;
                        }
                        if (col + 1 < Nact) {
                            C[(size_t)row * Nact + col + 1]       = v01;
                            C[(size_t)(row + 8) * Nact + col + 1] = v11;
                        }
                    }
                }
                if (Ohi) {   // split (optionally relu'd); Nact even here
                    float r00 = do_relu ? fmaxf(v00, 0.f) : v00;
                    float r01 = do_relu ? fmaxf(v01, 0.f) : v01;
                    float r10 = do_relu ? fmaxf(v10, 0.f) : v10;
                    float r11 = do_relu ? fmaxf(v11, 0.f) : v11;
                    __half h00, l00, h01, l01, h10, l10, h11, l11;
                    split_h(r00, h00, l00); split_h(r01, h01, l01);
                    split_h(r10, h10, l10); split_h(r11, h11, l11);
                    size_t i0 = (size_t)row * Nact + col;
                    size_t i1 = (size_t)(row + 8) * Nact + col;
                    *(__half2*)(Ohi + i0) = __halves2half2(h00, h01);
                    *(__half2*)(Ohi + i1) = __halves2half2(h10, h11);
                    *(__half2*)(Olo + i0) = __halves2half2(l00, l01);
                    *(__half2*)(Olo + i1) = __halves2half2(l10, l11);
                }
            }
        }
    }
}

// ---------------------------------------------------------------------------
// All big weight transposes in ONE launch. z: 0..11 SRU, 12 W3, 13 W4.
// ---------------------------------------------------------------------------
__global__ __launch_bounds__(256)
void transpose_all(const float* __restrict__ sru_W,
                   const float* __restrict__ W3,
                   const float* __restrict__ W4,
                   __half* __restrict__ Wt,
                   __half* __restrict__ W3t,
                   __half* __restrict__ W4t)
{
    int z = blockIdx.z;
    const float* W;
    __half* hi;
    int Nsrc, Npad;
    if (z < LL) {
        W = sru_W + (size_t)z * HH * N3H;
        hi = Wt + (size_t)z * N3H * HH;
        Nsrc = N3H; Npad = N3H;
    } else if (z == LL) {
        W = W3; hi = W3t; Nsrc = HH; Npad = HH;
    } else {
        W = W4; hi = W4t; Nsrc = NOUT; Npad = NPAD4;
    }

    int nb = blockIdx.x * 32, kb = blockIdx.y * 64;
    if (nb >= Npad) return;

    __shared__ float t[64][33];
    int tx = threadIdx.x & 31;
    int ty = threadIdx.x >> 5;
    int n = nb + tx;
#pragma unroll
    for (int i = 0; i < 8; i++) {
        int kk = ty * 8 + i;
        t[kk][tx] = (n < Nsrc) ? W[(size_t)(kb + kk) * Nsrc + n] : 0.f;
    }
    __syncthreads();
#pragma unroll
    for (int p = 0; p < 4; p++) {
        int idx = threadIdx.x + p * 256;
        int nl = idx >> 5, kp = idx & 31;
        float v0 = t[2 * kp][nl];
        float v1 = t[2 * kp + 1][nl];
        size_t o = ((size_t)(nb + nl) * HH + kb) / 2 + kp;
        ((__half2*)hi)[o] = __halves2half2(__float2half_rn(v0), __float2half_rn(v1));
    }
}

// ---------------------------------------------------------------------------
// W1 [200,1024] -> W1h/W1l [1024 n][256 k] (hi/lo, zero-padded k>=200)
// ---------------------------------------------------------------------------
__global__ __launch_bounds__(256)
void w1_prep(const float* __restrict__ W1,
             __half* __restrict__ W1h, __half* __restrict__ W1l)
{
    int nb = blockIdx.x * 32, kb = blockIdx.y * 64;
    __shared__ float t[64][33];
    int tx = threadIdx.x & 31;
    int ty = threadIdx.x >> 5;
    int n = nb + tx;
#pragma unroll
    for (int i = 0; i < 8; i++) {
        int kk = kb + ty * 8 + i;
        t[ty * 8 + i][tx] = (kk < DIN) ? W1[(size_t)kk * HH + n] : 0.f;
    }
    __syncthreads();
#pragma unroll
    for (int p = 0; p < 4; p++) {
        int idx = threadIdx.x + p * 256;
        int nl = idx >> 5, kp = idx & 31;
        float v0 = t[2 * kp][nl];
        float v1 = t[2 * kp + 1][nl];
        __half h0, l0, h1, l1;
        split_h(v0, h0, l0);
        split_h(v1, h1, l1);
        size_t o = ((size_t)(nb + nl) * K1P + kb) / 2 + kp;
        ((__half2*)W1h)[o] = __halves2half2(h0, h1);
        ((__half2*)W1l)[o] = __halves2half2(l0, l1);
    }
}

// ---------------------------------------------------------------------------
// x [B,T,200] -> Xh/Xl [m=t*BB+b][256] hi/lo (zero-padded k>=200)
// ---------------------------------------------------------------------------
__global__ __launch_bounds__(256)
void x_prep(const float* __restrict__ x,
            __half* __restrict__ Xh, __half* __restrict__ Xl)
{
    int i = blockIdx.x * blockDim.x + threadIdx.x;
    if (i >= MM * K1P) return;
    int m = i >> 8, k = i & (K1P - 1);
    int b = m & (BB - 1), t = m >> 7;
    float v = (k < DIN) ? x[(size_t)(b * TT + t) * DIN + k] : 0.f;
    __half h, l;
    split_h(v, h, l);
    Xh[i] = h;
    Xl[i] = l;
}

// ---------------------------------------------------------------------------
// SRU scan, templated on LAST; 32-bit offsets with constant per-t strides.
// x_tilde fp32 Ux, gate pre-acts fp16 Ufr. Bias+sigmoid here. Prefetch t+1.
// ---------------------------------------------------------------------------
template<int LAST>
__global__ __launch_bounds__(256)
void sru_scan(const float* __restrict__ Ux, const __half* __restrict__ Ufr,
              const float* __restrict__ b_l, const float* __restrict__ c0,
              const __half* __restrict__ Xhi, const __half* __restrict__ Xlo,
              __half* __restrict__ Ohi, __half* __restrict__ Olo,
              float* __restrict__ c_out)
{
    int idx = blockIdx.x * blockDim.x + threadIdx.x;
    int j = idx & (HH - 1);
    int b = idx >> 10;

    float bf = b_l[j];
    float br = b_l[HH + j];
    float c  = c0[idx];

    const int sU = BB * HH;            // per-t stride, Ux/Xhi/Xlo
    const int sG = BB * 2 * HH;        // per-t stride, Ufr
    int uoff = b * HH + j;             // t=0
    int goff = b * 2 * HH + j;
    int ooff = LAST ? (b * TT) * HH + j : uoff;
    const int sO = LAST ? HH : sU;

    // preload t = 0
    float xt = Ux[uoff];
    float fp = __half2float(Ufr[goff]);
    float rp = __half2float(Ufr[goff + HH]);
    float xinh = __half2float(Xhi[uoff]);
    float xinl = __half2float(Xlo[uoff]);

#pragma unroll
    for (int t = 0; t < TT; t++) {
        // prefetch t+1 before the serial compute chain
        float xt_n = 0.f, fp_n = 0.f, rp_n = 0.f, xinh_n = 0.f, xinl_n = 0.f;
        if (t + 1 < TT) {
            int u2 = uoff + sU, g2 = goff + sG;
            xt_n = Ux[u2];
            fp_n = __half2float(Ufr[g2]);
            rp_n = __half2float(Ufr[g2 + HH]);
            xinh_n = __half2float(Xhi[u2]);
            xinl_n = __half2float(Xlo[u2]);
        }

        float f = 1.f / (1.f + __expf(-(fp + bf)));
        float r = 1.f / (1.f + __expf(-(rp + br)));
        c = f * c + (1.f - f) * xt;
        float e2 = __expf(2.f * c);
        float th = 1.f - 2.f / (e2 + 1.f);
        float xin_v = xinh + xinl;
        float hv = r * th + (1.f - r) * xin_v;

        __half hb, lb;
        split_h(hv, hb, lb);
        Ohi[ooff] = hb;
        Olo[ooff] = lb;

        uoff += sU; goff += sG; ooff += sO;
        xt = xt_n; fp = fp_n; rp = rp_n; xinh = xinh_n; xinl = xinl_n;
    }
    c_out[idx] = c;
}

// ---------------------------------------------------------------------------
// kernel_launch
// ---------------------------------------------------------------------------
extern "C" void kernel_launch(void* const* d_in, const int* in_sizes, int n_in,
                              void* d_out, int out_size)
{
    const float* x      = (const float*)d_in[0];
    const float* hidden = (const float*)d_in[1];
    const float* W1     = (const float*)d_in[2];
    const float* b1     = (const float*)d_in[3];
    const float* sru_W  = (const float*)d_in[4];
    const float* sru_b  = (const float*)d_in[5];
    const float* W3     = (const float*)d_in[6];
    const float* b3     = (const float*)d_in[7];
    const float* W4     = (const float*)d_in[8];
    const float* b4     = (const float*)d_in[9];

    float* out = (float*)d_out;
    float* logits_out = out;                          // [2560, 1095]
    float* fx_out     = out + (size_t)MM * NOUT;      // [2560, 1024]
    float* hid_out    = fx_out + (size_t)MM * HH;     // [12, 128, 1024]

    float* Ux;
    __half *Ufr, *Ahi, *Alo, *Bhi, *Blo, *Wt, *W3t, *W4t, *Xh, *Xl, *W1h, *W1l;
    cudaGetSymbolAddress((void**)&Ux, g_Ux);
    cudaGetSymbolAddress((void**)&Ufr, g_Ufr);
    cudaGetSymbolAddress((void**)&Ahi, g_Ahi);
    cudaGetSymbolAddress((void**)&Alo, g_Alo);
    cudaGetSymbolAddress((void**)&Bhi, g_Bhi);
    cudaGetSymbolAddress((void**)&Blo, g_Blo);
    cudaGetSymbolAddress((void**)&Wt, g_Wt);
    cudaGetSymbolAddress((void**)&W3t, g_W3t);
    cudaGetSymbolAddress((void**)&W4t, g_W4t);
    cudaGetSymbolAddress((void**)&Xh, g_Xh);
    cudaGetSymbolAddress((void**)&Xl, g_Xl);
    cudaGetSymbolAddress((void**)&W1h, g_W1h);
    cudaGetSymbolAddress((void**)&W1l, g_W1l);

    const int SM2 = NSTAGE * (2 * TILE_AH + 128 * 128);          // 98304
    const int SMD = NSTAGE * (2 * TILE_AH + 2 * 64 * 128);       // 98304
    cudaFuncSetAttribute((const void*)gemm_mma<HH, false, 128>,
                         cudaFuncAttributeMaxDynamicSharedMemorySize, SM2);
    cudaFuncSetAttribute((const void*)gemm_mma<K1P, true, 64>,
                         cudaFuncAttributeMaxDynamicSharedMemorySize, SMD);

    dim3 blk(256);
    const int NO_SPLIT = 1 << 30;

    // 0) weight/input prep
    transpose_all<<<dim3(N3H / 32, HH / 64, LL + 2), blk>>>(
        sru_W, W3, W4, Wt, W3t, W4t);
    w1_prep<<<dim3(HH / 32, K1P / 64), blk>>>(W1, W1h, W1l);
    x_prep<<<(MM * K1P) / 256, blk>>>(x, Xh, Xl);

    // 1) dense1 (exact 3-MMA fp16, BN=64 for 2 CTA/SM): split(x@W1+b1)->Ahi/Alo
    gemm_mma<K1P, true, 64><<<dim3(HH / 64, MM / 64), blk, SMD>>>(
        Xh, Xl, W1h, W1l, b1, nullptr, HH, NO_SPLIT, 0,
        Ahi, Alo, nullptr, nullptr);

    // 2) SRU layers: x_tilde (<1024) 2-MMA -> Ux fp32; gates 1-MMA -> fp16 raw
    for (int l = 0; l < LL; l++) {
        gemm_mma<HH, false, 128><<<dim3(N3H / 128, MM / 64), blk, SM2>>>(
            Ahi, Alo, Wt + (size_t)l * N3H * HH, nullptr,
            nullptr, nullptr, N3H, HH, 0, nullptr, nullptr,
            Ux, Ufr);
        if (l == LL - 1) {
            sru_scan<1><<<(BB * HH) / 256, blk>>>(
                Ux, Ufr, sru_b + (size_t)l * 2 * HH, hidden + (size_t)l * BB * HH,
                Ahi, Alo, Bhi, Blo, hid_out + (size_t)l * BB * HH);
        } else {
            sru_scan<0><<<(BB * HH) / 256, blk>>>(
                Ux, Ufr, sru_b + (size_t)l * 2 * HH, hidden + (size_t)l * BB * HH,
                Ahi, Alo, Ahi, Alo, hid_out + (size_t)l * BB * HH);
        }
    }

    // 3) fx = h([B,T]) @ W3 + b3, fused relu+split into Ahi/Alo
    gemm_mma<HH, false, 128><<<dim3(HH / 128, MM / 64), blk, SM2>>>(
        Bhi, Blo, W3t, nullptr, b3, fx_out, HH, NO_SPLIT, 1,
        Ahi, Alo, nullptr, nullptr);

    // 4) logits = relu(fx) @ W4 + b4
    gemm_mma<HH, false, 128><<<dim3(NPAD4 / 128, MM / 64), blk, SM2>>>(
        Ahi, Alo, W4t, nullptr, b4, logits_out, NOUT, NO_SPLIT, 0,
        nullptr, nullptr, nullptr, nullptr);
}